// round 14
// baseline (speedup 1.0000x reference)
#include <cuda_runtime.h>
#include <cuda_fp16.h>
#include <stdint.h>

#define D_MODEL 768
#define D_FF    3072
#define MROWS   8192   // B*S = 4*2048
#define LN_EPS  1e-12f
#define GRIDP   296    // persistent CTA count (2 per SM on 148-SM die)

// ---------------- scratch (__device__ globals; no runtime allocation) ----------
__device__ float   g_c[D_MODEL];
__device__ __half  g_A[(size_t)MROWS * D_MODEL];    // LN1 output (also ln2 residual)
__device__ __half  g_Wi[(size_t)D_FF * D_MODEL];
__device__ __half  g_Wf[(size_t)D_MODEL * D_FF];
__device__ __half  g_H[(size_t)MROWS * D_FF];
__device__ __half  g_P[(size_t)MROWS * D_MODEL];
__device__ __half  g_P2[(size_t)MROWS * D_MODEL];
__device__ __half  g_P3[(size_t)MROWS * D_MODEL];
__device__ unsigned g_ctr1, g_ctr2;
__device__ unsigned g_rowcnt[64];    // gemm1 completion per 128-row block (24 tiles)
__device__ unsigned g_rowcnt2[64];   // gemm2 completion per 128-row block (18 tiles)

// ---------------- helpers --------------------------------------------------------
__device__ __forceinline__ float gelu_exact(float x) {
    return 0.5f * x * (1.0f + erff(x * 0.7071067811865476f));
}

__device__ __forceinline__ void ldsm4(uint32_t (&r)[4], uint32_t addr) {
    asm volatile("ldmatrix.sync.aligned.m8n8.x4.shared.b16 {%0,%1,%2,%3}, [%4];"
                 : "=r"(r[0]), "=r"(r[1]), "=r"(r[2]), "=r"(r[3])
                 : "r"(addr));
}

__device__ __forceinline__ void mma_f16(float (&c)[4], const uint32_t (&a)[4],
                                        uint32_t b0, uint32_t b1) {
    asm volatile(
        "mma.sync.aligned.m16n8k16.row.col.f32.f16.f16.f32 "
        "{%0,%1,%2,%3},{%4,%5,%6,%7},{%8,%9},{%0,%1,%2,%3};"
        : "+f"(c[0]), "+f"(c[1]), "+f"(c[2]), "+f"(c[3])
        : "r"(a[0]), "r"(a[1]), "r"(a[2]), "r"(a[3]), "r"(b0), "r"(b1));
}

__device__ __forceinline__ void cp16(uint32_t saddr, const void* g) {
    asm volatile("cp.async.cg.shared.global [%0], [%1], 16;" ::"r"(saddr), "l"(g));
}

// warp butterfly reduce (all lanes get result)
__device__ __forceinline__ void warp_reduce2(float& s, float& s2) {
    #pragma unroll
    for (int o = 16; o; o >>= 1) {
        s  += __shfl_xor_sync(0xffffffffu, s,  o);
        s2 += __shfl_xor_sync(0xffffffffu, s2, o);
    }
}

// ---------------- small kernels --------------------------------------------------
// also resets the dynamic-scheduler state each replay
__global__ void rowsum_kernel(const float* __restrict__ Wo, const float* __restrict__ bo) {
    if (blockIdx.x == 0) {
        if (threadIdx.x == 0) { g_ctr1 = 0; g_ctr2 = 0; }
        if (threadIdx.x < 64) { g_rowcnt[threadIdx.x] = 0; g_rowcnt2[threadIdx.x] = 0; }
    }
    int gw = (blockIdx.x * blockDim.x + threadIdx.x) >> 5;
    int lane = threadIdx.x & 31;
    if (gw >= D_MODEL) return;
    const float* r = Wo + (size_t)gw * D_MODEL;
    float s = 0.f;
    for (int j = lane; j < D_MODEL; j += 32) s += r[j];
    #pragma unroll
    for (int o = 16; o; o >>= 1) s += __shfl_down_sync(0xffffffffu, s, o);
    if (lane == 0) g_c[gw] = 0.01f * s + bo[gw];
}

// merged: blocks [0,1024) = ln1 (warp per row, 8 rows/block);
//         blocks [1024, 1024+4608) = weight conversion
#define LN1_BLOCKS  1024
#define CONV_BLOCKS 4608   // 2*(D_FF*D_MODEL/4)/256
__global__ void __launch_bounds__(256) prep_kernel(
        const float* __restrict__ hidden,
        const float* __restrict__ gam, const float* __restrict__ bet,
        const float* __restrict__ Wi, const float* __restrict__ Wf) {
    int bid = blockIdx.x;
    if (bid < LN1_BLOCKS) {
        int warp = threadIdx.x >> 5, lane = threadIdx.x & 31;
        int row = bid * 8 + warp;
        const float4* xr = reinterpret_cast<const float4*>(hidden + (size_t)row * D_MODEL);
        const float4* cr = reinterpret_cast<const float4*>(g_c);
        float4 v[6];
        float s = 0.f, s2 = 0.f;
        #pragma unroll
        for (int i = 0; i < 6; i++) {
            float4 x = xr[lane + 32 * i];
            float4 c = cr[lane + 32 * i];
            x.x += c.x; x.y += c.y; x.z += c.z; x.w += c.w;
            v[i] = x;
            s  += x.x + x.y + x.z + x.w;
            s2 += x.x * x.x + x.y * x.y + x.z * x.z + x.w * x.w;
        }
        warp_reduce2(s, s2);
        float mean = s * (1.f / D_MODEL);
        float var = s2 * (1.f / D_MODEL) - mean * mean;
        float rstd = rsqrtf(var + LN_EPS);
        uint2* outp = reinterpret_cast<uint2*>(g_A + (size_t)row * D_MODEL);
        const float4* gr = reinterpret_cast<const float4*>(gam);
        const float4* br = reinterpret_cast<const float4*>(bet);
        #pragma unroll
        for (int i = 0; i < 6; i++) {
            float4 g = gr[lane + 32 * i];
            float4 b = br[lane + 32 * i];
            float4 a;
            a.x = (v[i].x - mean) * rstd * g.x + b.x;
            a.y = (v[i].y - mean) * rstd * g.y + b.y;
            a.z = (v[i].z - mean) * rstd * g.z + b.z;
            a.w = (v[i].w - mean) * rstd * g.w + b.w;
            __half2 h0 = __floats2half2_rn(a.x, a.y);
            __half2 h1 = __floats2half2_rn(a.z, a.w);
            outp[lane + 32 * i] = make_uint2(*(uint32_t*)&h0, *(uint32_t*)&h1);
        }
    } else {
        constexpr int n4 = D_FF * D_MODEL / 4;
        int i = (bid - LN1_BLOCKS) * 256 + threadIdx.x;
        const float* src;
        __half* Wh;
        int j;
        if (i < n4) { src = Wi; Wh = g_Wi; j = i; }
        else        { src = Wf; Wh = g_Wf; j = i - n4; }
        float4 v = reinterpret_cast<const float4*>(src)[j];
        __half2 h01 = __floats2half2_rn(v.x, v.y);
        __half2 h23 = __floats2half2_rn(v.z, v.w);
        reinterpret_cast<uint2*>(Wh)[j] =
            make_uint2(*(uint32_t*)&h01, *(uint32_t*)&h23);
    }
}

// ---------------- fused persistent kernel (gemm1 + gemm2 + ln2) ------------------
// Tiles 0..1535:    gemm1  C = gelu(A@Wi^T + bi) -> g_H    (K=768,  KT=12)
// Tiles 1536..2687: gemm2  split-K3 fp16 partials -> g_P*  (Kc=1024, KT=16)
// Phase 3 (ctr2):   ln2 tiles, 64 x 128 rows, gated by g_rowcnt2 (18 producers)
#define BK 64
#define LDT 72                        // padded smem row elems; 144B stride
#define TILE_B 18432                  // 128*72*2 per operand
#define STAGE_B 36864
#define NSTAGE 3
#define SMEM_GEMM (NSTAGE * STAGE_B + 16)
#define NT1 1536
#define NT_ALL 2688

__global__ void __launch_bounds__(128, 2) gemm_fused(
        const float* __restrict__ bias1, const float* __restrict__ bf,
        const float* __restrict__ ln2g, const float* __restrict__ ln2b,
        float* __restrict__ out) {
    extern __shared__ char smem[];
    const uint32_t smem_u32 = (uint32_t)__cvta_generic_to_shared(smem);
    volatile unsigned* sm_next = (volatile unsigned*)(smem + NSTAGE * STAGE_B);
    volatile unsigned* sm_flag = (volatile unsigned*)(smem + NSTAGE * STAGE_B + 4);

    const int tid = threadIdx.x;
    const int lane = tid & 31;
    const int warp = tid >> 5;
    const int wm = warp >> 1;
    const int wn = warp & 1;
    const int lrow = tid >> 3;        // 0..15
    const int lcol = tid & 7;         // 0..7

    __shared__ unsigned s_t0;
    if (tid == 0) s_t0 = atomicAdd(&g_ctr1, 1u);
    __syncthreads();
    unsigned t = s_t0;

    auto decode = [&](unsigned tt, int& mb, int& nb, int& kb, int& kk, int& ktn, bool& is1) {
        if (tt < NT1) {
            is1 = true;  nb = (tt % 24) * 128; mb = (tt / 24) * 128; kb = 0;
            kk = D_MODEL; ktn = 12;
        } else {
            unsigned u = tt - NT1;
            is1 = false; nb = (u % 6) * 128; mb = ((u / 6) % 64) * 128; kb = (u / 384) * 1024;
            kk = D_FF; ktn = 16;
        }
    };

    if (t < NT_ALL) {
        int m_blk, n_blk, k_base, K, KT;
        bool is1;
        decode(t, m_blk, n_blk, k_base, K, KT, is1);   // first 296 tiles are gemm1

        const __half* pA = (is1 ? g_A : g_H) + (size_t)(m_blk + lrow) * K + lcol * 8 + k_base;
        const __half* pB = (is1 ? g_Wi : g_Wf) + (size_t)(n_blk + lrow) * K + lcol * 8 + k_base;

        const uint32_t sm_woff = (uint32_t)(lrow * 144 + lcol * 16);

        auto load_part = [&](int s, int koff, const __half* a, const __half* b, int part,
                             int stride) {
            uint32_t base = smem_u32 + s * STAGE_B + sm_woff + (uint32_t)(part * 32 * 144);
            const __half* ga = a + (size_t)(part * 32) * stride + koff;
            const __half* gb = b + (size_t)(part * 32) * stride + koff;
            cp16(base,                       ga);
            cp16(base + TILE_B,              gb);
            cp16(base + 16 * 144,            ga + (size_t)16 * stride);
            cp16(base + 16 * 144 + TILE_B,   gb + (size_t)16 * stride);
        };

        const int a_row = wm * 64 + (lane & 15);
        const int a_k = (lane >> 4) * 8;
        const int b_row = wn * 64 + (lane & 7) + ((lane >> 4) & 1) * 8;
        const int b_k = ((lane >> 3) & 1) * 8;

        uint32_t aF[2][4][4], bF[2][4][4];
        auto ldsm_frags = [&](int buf, uint32_t base, int ks) {
            const int k0 = ks * 16;
            #pragma unroll
            for (int mt = 0; mt < 4; ++mt)
                ldsm4(aF[buf][mt], base + (uint32_t)((a_row + mt * 16) * LDT + k0 + a_k) * 2);
            #pragma unroll
            for (int np = 0; np < 4; ++np)
                ldsm4(bF[buf][np], base + TILE_B +
                                       (uint32_t)((b_row + np * 16) * LDT + k0 + b_k) * 2);
        };

        #pragma unroll
        for (int p = 0; p < 4; ++p) load_part(0, 0, pA, pB, p, K);
        asm volatile("cp.async.commit_group;");
        #pragma unroll
        for (int p = 0; p < 4; ++p) load_part(1, BK, pA, pB, p, K);
        asm volatile("cp.async.commit_group;");
        asm volatile("cp.async.wait_group 1;");
        __syncthreads();
        ldsm_frags(0, smem_u32, 0);

        int cur_st = 0;
        for (;;) {
            if (tid == 0) sm_next[0] = atomicAdd(&g_ctr1, 1u);

            float acc[4][8][4];
            #pragma unroll
            for (int a = 0; a < 4; a++)
                #pragma unroll
                for (int b = 0; b < 8; b++)
                    #pragma unroll
                    for (int c = 0; c < 4; c++) acc[a][b][c] = 0.f;

            unsigned t_next = 0;
            bool has_next = false;
            bool prefetched = true;
            int nm = 0, nn2 = 0, nk = 0, Kn = K, KTn = KT;
            bool is1n = is1;
            const __half *pAn = pA, *pBn = pB;

            for (int kt = 0; kt < KT; ++kt) {
                if (kt == KT - 2) {
                    t_next = sm_next[0];
                    has_next = t_next < NT_ALL;
                    if (has_next) {
                        decode(t_next, nm, nn2, nk, Kn, KTn, is1n);
                        if (!is1n) {
                            if (tid == 0)
                                sm_flag[0] = (g_rowcnt[nm >> 7] >= 24u) ? 1u : 0u;
                            __syncthreads();
                            prefetched = (sm_flag[0] != 0u);
                        }
                        pAn = (is1n ? g_A : g_H) + (size_t)(nm + lrow) * Kn + lcol * 8 + nk;
                        pBn = (is1n ? g_Wi : g_Wf) + (size_t)(nn2 + lrow) * Kn + lcol * 8 + nk;
                    }
                }

                const uint32_t base = smem_u32 + cur_st * STAGE_B;
                int p_st = cur_st + 2; if (p_st >= NSTAGE) p_st -= NSTAGE;
                const bool tail = (kt + 2 >= KT);
                const bool do_cp = !tail || (has_next && prefetched);
                const int koff = (tail ? (kt + 2 - KT) : (kt + 2)) * BK;
                const __half* qA = tail ? pAn : pA;
                const __half* qB = tail ? pBn : pB;
                const int qK = tail ? Kn : K;

                #pragma unroll
                for (int ks = 0; ks < 4; ++ks) {
                    const int cur = ks & 1;
                    if (ks < 3) ldsm_frags(cur ^ 1, base, ks + 1);
                    #pragma unroll
                    for (int mt = 0; mt < 2; ++mt)
                        #pragma unroll
                        for (int nt = 0; nt < 8; ++nt) {
                            uint32_t b0 = bF[cur][nt >> 1][(nt & 1) * 2];
                            uint32_t b1 = bF[cur][nt >> 1][(nt & 1) * 2 + 1];
                            mma_f16(acc[mt][nt], aF[cur][mt], b0, b1);
                        }
                    if (do_cp) load_part(p_st, koff, qA, qB, ks, qK);
                    if (ks == 3) asm volatile("cp.async.commit_group;");
                    #pragma unroll
                    for (int mt = 2; mt < 4; ++mt)
                        #pragma unroll
                        for (int nt = 0; nt < 8; ++nt) {
                            uint32_t b0 = bF[cur][nt >> 1][(nt & 1) * 2];
                            uint32_t b1 = bF[cur][nt >> 1][(nt & 1) * 2 + 1];
                            mma_f16(acc[mt][nt], aF[cur][mt], b0, b1);
                        }
                }

                asm volatile("cp.async.wait_group 1;");
                __syncthreads();
                int nxt_st = cur_st + 1; if (nxt_st >= NSTAGE) nxt_st -= NSTAGE;
                if (kt + 1 < KT || (has_next && prefetched))
                    ldsm_frags(0, smem_u32 + nxt_st * STAGE_B, 0);
                cur_st = nxt_st;
            }

            // ---------------- epilogue ----------------
            if (is1) {
                #pragma unroll
                for (int mt = 0; mt < 4; ++mt)
                    #pragma unroll
                    for (int nt = 0; nt < 8; ++nt) {
                        int n = n_blk + wn * 64 + nt * 8 + (lane & 3) * 2;
                        float b0 = bias1[n], b1 = bias1[n + 1];
                        #pragma unroll
                        for (int h = 0; h < 2; ++h) {
                            int m = m_blk + wm * 64 + mt * 16 + (lane >> 2) + h * 8;
                            float x0 = acc[mt][nt][2 * h + 0] + b0;
                            float x1 = acc[mt][nt][2 * h + 1] + b1;
                            __half2 hv = __floats2half2_rn(gelu_exact(x0), gelu_exact(x1));
                            *reinterpret_cast<__half2*>(&g_H[(size_t)m * D_FF + n]) = hv;
                        }
                    }
                __threadfence();
                __syncthreads();
                if (tid == 0) atomicAdd(&g_rowcnt[m_blk >> 7], 1u);
            } else {
                __half* Pout = (k_base == 0) ? g_P : (k_base == 1024 ? g_P2 : g_P3);
                #pragma unroll
                for (int mt = 0; mt < 4; ++mt)
                    #pragma unroll
                    for (int nt = 0; nt < 8; ++nt) {
                        int n = n_blk + wn * 64 + nt * 8 + (lane & 3) * 2;
                        #pragma unroll
                        for (int h = 0; h < 2; ++h) {
                            int m = m_blk + wm * 64 + mt * 16 + (lane >> 2) + h * 8;
                            __half2 hv = __floats2half2_rn(acc[mt][nt][2 * h],
                                                           acc[mt][nt][2 * h + 1]);
                            *reinterpret_cast<__half2*>(&Pout[(size_t)m * D_MODEL + n]) = hv;
                        }
                    }
                __threadfence();
                __syncthreads();
                if (tid == 0) atomicAdd(&g_rowcnt2[m_blk >> 7], 1u);
            }

            if (!has_next) break;

            if (!prefetched) {
                volatile unsigned* rc = &g_rowcnt[nm >> 7];
                while (*rc < 24u) { }
                __threadfence();
                __syncthreads();
                int st1 = cur_st + 1; if (st1 >= NSTAGE) st1 -= NSTAGE;
                #pragma unroll
                for (int p = 0; p < 4; ++p) load_part(cur_st, 0, pAn, pBn, p, Kn);
                asm volatile("cp.async.commit_group;");
                #pragma unroll
                for (int p = 0; p < 4; ++p) load_part(st1, BK, pAn, pBn, p, Kn);
                asm volatile("cp.async.commit_group;");
                asm volatile("cp.async.wait_group 1;");
                __syncthreads();
                ldsm_frags(0, smem_u32 + cur_st * STAGE_B, 0);
            }

            t = t_next; m_blk = nm; n_blk = nn2; k_base = nk;
            K = Kn; KT = KTn; is1 = is1n;
            pA = pAn; pB = pBn;
        }
    }

    // ---------------- phase 3: ln2 tiles (64 x 128 rows) -------------------------
    for (;;) {
        if (tid == 0) s_t0 = atomicAdd(&g_ctr2, 1u);
        __syncthreads();
        unsigned lt = s_t0;
        __syncthreads();
        if (lt >= 64u) break;

        if (tid == 0) {
            volatile unsigned* rc = &g_rowcnt2[lt];
            while (*rc < 18u) { }
        }
        __syncthreads();
        __threadfence();

        const float4* bfr = reinterpret_cast<const float4*>(bf);
        const float4* gr  = reinterpret_cast<const float4*>(ln2g);
        const float4* br  = reinterpret_cast<const float4*>(ln2b);
        for (int r = warp; r < 128; r += 4) {
            int row = (int)lt * 128 + r;
            size_t rbase = (size_t)row * (D_MODEL / 4);
            const uint2* p0 = reinterpret_cast<const uint2*>(g_P)  + rbase;
            const uint2* p1 = reinterpret_cast<const uint2*>(g_P2) + rbase;
            const uint2* p2 = reinterpret_cast<const uint2*>(g_P3) + rbase;
            const uint2* pa = reinterpret_cast<const uint2*>(g_A)  + rbase;
            float4 v[6];
            float s = 0.f, s2 = 0.f;
            #pragma unroll
            for (int i = 0; i < 6; i++) {
                int idx = lane + 32 * i;
                uint2 u0 = p0[idx], u1 = p1[idx], u2 = p2[idx], ua = pa[idx];
                float2 a0 = __half22float2(*(__half2*)&u0.x), a1 = __half22float2(*(__half2*)&u0.y);
                float2 b0 = __half22float2(*(__half2*)&u1.x), b1 = __half22float2(*(__half2*)&u1.y);
                float2 c0 = __half22float2(*(__half2*)&u2.x), c1 = __half22float2(*(__half2*)&u2.y);
                float2 t0 = __half22float2(*(__half2*)&ua.x), t1 = __half22float2(*(__half2*)&ua.y);
                float4 bv = bfr[idx];
                float4 x;
                x.x = a0.x + b0.x + c0.x + t0.x + bv.x;
                x.y = a0.y + b0.y + c0.y + t0.y + bv.y;
                x.z = a1.x + b1.x + c1.x + t1.x + bv.z;
                x.w = a1.y + b1.y + c1.y + t1.y + bv.w;
                v[i] = x;
                s  += x.x + x.y + x.z + x.w;
                s2 += x.x * x.x + x.y * x.y + x.z * x.z + x.w * x.w;
            }
            warp_reduce2(s, s2);
            float mean = s * (1.f / D_MODEL);
            float var = s2 * (1.f / D_MODEL) - mean * mean;
            float rstd = rsqrtf(var + LN_EPS);
            float4* op = reinterpret_cast<float4*>(out) + rbase;
            #pragma unroll
            for (int i = 0; i < 6; i++) {
                int idx = lane + 32 * i;
                float4 g = gr[idx];
                float4 b = br[idx];
                float4 o;
                o.x = (v[i].x - mean) * rstd * g.x + b.x;
                o.y = (v[i].y - mean) * rstd * g.y + b.y;
                o.z = (v[i].z - mean) * rstd * g.z + b.z;
                o.w = (v[i].w - mean) * rstd * g.w + b.w;
                op[idx] = o;
            }
        }
        __syncthreads();
    }
}

// ---------------- launch ---------------------------------------------------------
extern "C" void kernel_launch(void* const* d_in, const int* in_sizes, int n_in,
                              void* d_out, int out_size) {
    (void)in_sizes; (void)n_in; (void)out_size;
    const float* hidden = (const float*)d_in[0];
    // d_in[1..6] = Wq,bq,Wk,bk,Wv,bv — dead (q/k/v overwritten by constants)
    const float* Wo   = (const float*)d_in[7];
    const float* bo   = (const float*)d_in[8];
    const float* ln1g = (const float*)d_in[9];
    const float* ln1b = (const float*)d_in[10];
    const float* Wi   = (const float*)d_in[11];
    const float* bi   = (const float*)d_in[12];
    const float* Wf   = (const float*)d_in[13];
    const float* bf_  = (const float*)d_in[14];
    const float* ln2g = (const float*)d_in[15];
    const float* ln2b = (const float*)d_in[16];
    float* out = (float*)d_out;

    cudaFuncSetAttribute(gemm_fused, cudaFuncAttributeMaxDynamicSharedMemorySize, SMEM_GEMM);

    rowsum_kernel<<<96, 256>>>(Wo, bo);
    prep_kernel<<<LN1_BLOCKS + CONV_BLOCKS, 256>>>(hidden, ln1g, ln1b, Wi, Wf);

    gemm_fused<<<GRIDP, 128, SMEM_GEMM>>>(bi, bf_, ln2g, ln2b, out);
}

// round 15
// speedup vs baseline: 1.1158x; 1.1158x over previous
#include <cuda_runtime.h>
#include <cuda_fp16.h>
#include <stdint.h>

#define D_MODEL 768
#define D_FF    3072
#define MROWS   8192   // B*S = 4*2048
#define LN_EPS  1e-12f
#define GRIDP   296    // persistent CTA count (2 per SM on 148-SM die)

// ---------------- scratch (__device__ globals; no runtime allocation) ----------
__device__ float   g_c[D_MODEL];
__device__ __half  g_A[(size_t)MROWS * D_MODEL];    // LN1 output (also ln2 residual)
__device__ __half  g_Wi[(size_t)D_FF * D_MODEL];
__device__ __half  g_Wf[(size_t)D_MODEL * D_FF];
__device__ __half  g_H[(size_t)MROWS * D_FF];
__device__ __half  g_P[(size_t)MROWS * D_MODEL];
__device__ __half  g_P2[(size_t)MROWS * D_MODEL];
__device__ __half  g_P3[(size_t)MROWS * D_MODEL];
__device__ unsigned g_ctr1;
__device__ unsigned g_rowcnt[64];   // gemm1 completion counters per 128-row block

// ---------------- helpers --------------------------------------------------------
__device__ __forceinline__ float gelu_exact(float x) {
    return 0.5f * x * (1.0f + erff(x * 0.7071067811865476f));
}

__device__ __forceinline__ void ldsm4(uint32_t (&r)[4], uint32_t addr) {
    asm volatile("ldmatrix.sync.aligned.m8n8.x4.shared.b16 {%0,%1,%2,%3}, [%4];"
                 : "=r"(r[0]), "=r"(r[1]), "=r"(r[2]), "=r"(r[3])
                 : "r"(addr));
}

__device__ __forceinline__ void mma_f16(float (&c)[4], const uint32_t (&a)[4],
                                        uint32_t b0, uint32_t b1) {
    asm volatile(
        "mma.sync.aligned.m16n8k16.row.col.f32.f16.f16.f32 "
        "{%0,%1,%2,%3},{%4,%5,%6,%7},{%8,%9},{%0,%1,%2,%3};"
        : "+f"(c[0]), "+f"(c[1]), "+f"(c[2]), "+f"(c[3])
        : "r"(a[0]), "r"(a[1]), "r"(a[2]), "r"(a[3]), "r"(b0), "r"(b1));
}

__device__ __forceinline__ void cp16(uint32_t saddr, const void* g) {
    asm volatile("cp.async.cg.shared.global [%0], [%1], 16;" ::"r"(saddr), "l"(g));
}

// warp butterfly reduce (all lanes get result)
__device__ __forceinline__ void warp_reduce2(float& s, float& s2) {
    #pragma unroll
    for (int o = 16; o; o >>= 1) {
        s  += __shfl_xor_sync(0xffffffffu, s,  o);
        s2 += __shfl_xor_sync(0xffffffffu, s2, o);
    }
}

// ---------------- small kernels --------------------------------------------------
// also resets the dynamic-scheduler state each replay; float4-vectorized rowsum
__global__ void rowsum_kernel(const float* __restrict__ Wo, const float* __restrict__ bo) {
    if (blockIdx.x == 0) {
        if (threadIdx.x == 0) g_ctr1 = 0;
        if (threadIdx.x < 64) g_rowcnt[threadIdx.x] = 0;
    }
    int gw = (blockIdx.x * blockDim.x + threadIdx.x) >> 5;
    int lane = threadIdx.x & 31;
    if (gw >= D_MODEL) return;
    const float4* r = reinterpret_cast<const float4*>(Wo + (size_t)gw * D_MODEL);
    float s = 0.f;
    #pragma unroll
    for (int i = 0; i < 6; i++) {
        float4 v = r[lane + 32 * i];
        s += v.x + v.y + v.z + v.w;
    }
    #pragma unroll
    for (int o = 16; o; o >>= 1) s += __shfl_down_sync(0xffffffffu, s, o);
    if (lane == 0) g_c[gw] = 0.01f * s + bo[gw];
}

// merged: blocks [0,1024) = ln1 (warp per row, 8 rows/block);
//         blocks [1024, 1024+4608) = weight conversion
#define LN1_BLOCKS  1024
#define CONV_BLOCKS 4608   // 2*(D_FF*D_MODEL/4)/256
__global__ void __launch_bounds__(256) prep_kernel(
        const float* __restrict__ hidden,
        const float* __restrict__ gam, const float* __restrict__ bet,
        const float* __restrict__ Wi, const float* __restrict__ Wf) {
    int bid = blockIdx.x;
    if (bid < LN1_BLOCKS) {
        int warp = threadIdx.x >> 5, lane = threadIdx.x & 31;
        int row = bid * 8 + warp;
        const float4* xr = reinterpret_cast<const float4*>(hidden + (size_t)row * D_MODEL);
        const float4* cr = reinterpret_cast<const float4*>(g_c);
        float4 v[6];
        float s = 0.f, s2 = 0.f;
        #pragma unroll
        for (int i = 0; i < 6; i++) {
            float4 x = xr[lane + 32 * i];
            float4 c = cr[lane + 32 * i];
            x.x += c.x; x.y += c.y; x.z += c.z; x.w += c.w;
            v[i] = x;
            s  += x.x + x.y + x.z + x.w;
            s2 += x.x * x.x + x.y * x.y + x.z * x.z + x.w * x.w;
        }
        warp_reduce2(s, s2);
        float mean = s * (1.f / D_MODEL);
        float var = s2 * (1.f / D_MODEL) - mean * mean;
        float rstd = rsqrtf(var + LN_EPS);
        uint2* outp = reinterpret_cast<uint2*>(g_A + (size_t)row * D_MODEL);
        const float4* gr = reinterpret_cast<const float4*>(gam);
        const float4* br = reinterpret_cast<const float4*>(bet);
        #pragma unroll
        for (int i = 0; i < 6; i++) {
            float4 g = gr[lane + 32 * i];
            float4 b = br[lane + 32 * i];
            float4 a;
            a.x = (v[i].x - mean) * rstd * g.x + b.x;
            a.y = (v[i].y - mean) * rstd * g.y + b.y;
            a.z = (v[i].z - mean) * rstd * g.z + b.z;
            a.w = (v[i].w - mean) * rstd * g.w + b.w;
            __half2 h0 = __floats2half2_rn(a.x, a.y);
            __half2 h1 = __floats2half2_rn(a.z, a.w);
            outp[lane + 32 * i] = make_uint2(*(uint32_t*)&h0, *(uint32_t*)&h1);
        }
    } else {
        constexpr int n4 = D_FF * D_MODEL / 4;
        int i = (bid - LN1_BLOCKS) * 256 + threadIdx.x;
        const float* src;
        __half* Wh;
        int j;
        if (i < n4) { src = Wi; Wh = g_Wi; j = i; }
        else        { src = Wf; Wh = g_Wf; j = i - n4; }
        float4 v = reinterpret_cast<const float4*>(src)[j];
        __half2 h01 = __floats2half2_rn(v.x, v.y);
        __half2 h23 = __floats2half2_rn(v.z, v.w);
        reinterpret_cast<uint2*>(Wh)[j] =
            make_uint2(*(uint32_t*)&h01, *(uint32_t*)&h23);
    }
}

// out = LN(P0 + P1 + P2 + A + bf); warp per row, 8 rows/block, uint4 half loads
__global__ void __launch_bounds__(256) ln2_kernel(
        const float* __restrict__ gam, const float* __restrict__ bet,
        const float* __restrict__ bf, float* __restrict__ out) {
    int warp = threadIdx.x >> 5, lane = threadIdx.x & 31;
    int row = blockIdx.x * 8 + warp;
    size_t rbase8 = (size_t)row * (D_MODEL / 8);   // uint4 = 8 halves
    const uint4* p0 = reinterpret_cast<const uint4*>(g_P)  + rbase8;
    const uint4* p1 = reinterpret_cast<const uint4*>(g_P2) + rbase8;
    const uint4* p2 = reinterpret_cast<const uint4*>(g_P3) + rbase8;
    const uint4* pa = reinterpret_cast<const uint4*>(g_A)  + rbase8;
    const float4* bfr = reinterpret_cast<const float4*>(bf);
    float4 v[6];
    float s = 0.f, s2 = 0.f;
    #pragma unroll
    for (int i = 0; i < 3; i++) {
        int idx = lane + 32 * i;               // uint4 index (8 halves)
        uint4 u0 = p0[idx], u1 = p1[idx], u2 = p2[idx], ua = pa[idx];
        const uint32_t* w0 = &u0.x;
        const uint32_t* w1 = &u1.x;
        const uint32_t* w2 = &u2.x;
        const uint32_t* wa = &ua.x;
        #pragma unroll
        for (int h = 0; h < 2; h++) {          // two float4 outputs per uint4
            float2 a0 = __half22float2(*(__half2*)&w0[2 * h]);
            float2 a1 = __half22float2(*(__half2*)&w0[2 * h + 1]);
            float2 b0 = __half22float2(*(__half2*)&w1[2 * h]);
            float2 b1 = __half22float2(*(__half2*)&w1[2 * h + 1]);
            float2 c0 = __half22float2(*(__half2*)&w2[2 * h]);
            float2 c1 = __half22float2(*(__half2*)&w2[2 * h + 1]);
            float2 t0 = __half22float2(*(__half2*)&wa[2 * h]);
            float2 t1 = __half22float2(*(__half2*)&wa[2 * h + 1]);
            float4 bv = bfr[2 * idx + h];
            float4 x;
            x.x = a0.x + b0.x + c0.x + t0.x + bv.x;
            x.y = a0.y + b0.y + c0.y + t0.y + bv.y;
            x.z = a1.x + b1.x + c1.x + t1.x + bv.z;
            x.w = a1.y + b1.y + c1.y + t1.y + bv.w;
            v[2 * i + h] = x;
            s  += x.x + x.y + x.z + x.w;
            s2 += x.x * x.x + x.y * x.y + x.z * x.z + x.w * x.w;
        }
    }
    warp_reduce2(s, s2);
    float mean = s * (1.f / D_MODEL);
    float var = s2 * (1.f / D_MODEL) - mean * mean;
    float rstd = rsqrtf(var + LN_EPS);
    const float4* gr = reinterpret_cast<const float4*>(gam);
    const float4* br = reinterpret_cast<const float4*>(bet);
    float4* op = reinterpret_cast<float4*>(out) + (size_t)row * (D_MODEL / 4);
    #pragma unroll
    for (int i = 0; i < 3; i++) {
        int idx = lane + 32 * i;
        #pragma unroll
        for (int h = 0; h < 2; h++) {
            int fi = 2 * idx + h;
            float4 g = gr[fi];
            float4 b = br[fi];
            float4 o;
            o.x = (v[2 * i + h].x - mean) * rstd * g.x + b.x;
            o.y = (v[2 * i + h].y - mean) * rstd * g.y + b.y;
            o.z = (v[2 * i + h].z - mean) * rstd * g.z + b.z;
            o.w = (v[2 * i + h].w - mean) * rstd * g.w + b.w;
            op[fi] = o;
        }
    }
}

// ---------------- fused persistent GEMM (both phases, one kernel) ----------------
// Tiles 0..1535:    gemm1  C = gelu(A@Wi^T + bi) -> g_H    (K=768,  KT=12)
// Tiles 1536..2687: gemm2  split-K3 fp16 partials -> g_P*  (Kc=1024, KT=16)
// Cross-phase dataflow guarded by g_rowcnt. The readiness check mid-tile is
// NON-BLOCKING; if not ready, the CTA finishes its tile (incl. its own rowcnt
// increment) and only then spins + refills -> provably deadlock-free.
#define BK 64
#define LDT 72                        // padded smem row elems; 144B stride
#define TILE_B 18432                  // 128*72*2 per operand
#define STAGE_B 36864
#define NSTAGE 3
#define SMEM_GEMM (NSTAGE * STAGE_B + 16)
#define NT1 1536
#define NT_ALL 2688

__global__ void __launch_bounds__(128, 2) gemm_fused(const float* __restrict__ bias1) {
    extern __shared__ char smem[];
    const uint32_t smem_u32 = (uint32_t)__cvta_generic_to_shared(smem);
    volatile unsigned* sm_next = (volatile unsigned*)(smem + NSTAGE * STAGE_B);
    volatile unsigned* sm_flag = (volatile unsigned*)(smem + NSTAGE * STAGE_B + 4);

    const int tid = threadIdx.x;
    const int lane = tid & 31;
    const int warp = tid >> 5;
    const int wm = warp >> 1;
    const int wn = warp & 1;
    const int lrow = tid >> 3;        // 0..15
    const int lcol = tid & 7;         // 0..7

    __shared__ unsigned s_t0;
    if (tid == 0) s_t0 = atomicAdd(&g_ctr1, 1u);
    __syncthreads();
    unsigned t = s_t0;
    if (t >= NT_ALL) return;

    auto decode = [&](unsigned tt, int& mb, int& nb, int& kb, int& kk, int& ktn, bool& is1) {
        if (tt < NT1) {
            is1 = true;  nb = (tt % 24) * 128; mb = (tt / 24) * 128; kb = 0;
            kk = D_MODEL; ktn = 12;
        } else {
            unsigned u = tt - NT1;
            is1 = false; nb = (u % 6) * 128; mb = ((u / 6) % 64) * 128; kb = (u / 384) * 1024;
            kk = D_FF; ktn = 16;
        }
    };

    int m_blk, n_blk, k_base, K, KT;
    bool is1;
    decode(t, m_blk, n_blk, k_base, K, KT, is1);   // first 296 tiles are all gemm1

    const __half* pA = (is1 ? g_A : g_H) + (size_t)(m_blk + lrow) * K + lcol * 8 + k_base;
    const __half* pB = (is1 ? g_Wi : g_Wf) + (size_t)(n_blk + lrow) * K + lcol * 8 + k_base;

    const uint32_t sm_woff = (uint32_t)(lrow * 144 + lcol * 16);

    // one quarter (2x16 rows of A and B) of a BK=64 slab; stride = row pitch (elems)
    auto load_part = [&](int s, int koff, const __half* a, const __half* b, int part,
                         int stride) {
        uint32_t base = smem_u32 + s * STAGE_B + sm_woff + (uint32_t)(part * 32 * 144);
        const __half* ga = a + (size_t)(part * 32) * stride + koff;
        const __half* gb = b + (size_t)(part * 32) * stride + koff;
        cp16(base,                       ga);
        cp16(base + TILE_B,              gb);
        cp16(base + 16 * 144,            ga + (size_t)16 * stride);
        cp16(base + 16 * 144 + TILE_B,   gb + (size_t)16 * stride);
    };

    const int a_row = wm * 64 + (lane & 15);
    const int a_k = (lane >> 4) * 8;
    const int b_row = wn * 64 + (lane & 7) + ((lane >> 4) & 1) * 8;
    const int b_k = ((lane >> 3) & 1) * 8;

    uint32_t aF[2][4][4], bF[2][4][4];
    auto ldsm_frags = [&](int buf, uint32_t base, int ks) {
        const int k0 = ks * 16;
        #pragma unroll
        for (int mt = 0; mt < 4; ++mt)
            ldsm4(aF[buf][mt], base + (uint32_t)((a_row + mt * 16) * LDT + k0 + a_k) * 2);
        #pragma unroll
        for (int np = 0; np < 4; ++np)
            ldsm4(bF[buf][np], base + TILE_B +
                                   (uint32_t)((b_row + np * 16) * LDT + k0 + b_k) * 2);
    };

    // preamble: slabs 0 and 1 of first tile; preload ks0 frags of slab 0
    #pragma unroll
    for (int p = 0; p < 4; ++p) load_part(0, 0, pA, pB, p, K);
    asm volatile("cp.async.commit_group;");
    #pragma unroll
    for (int p = 0; p < 4; ++p) load_part(1, BK, pA, pB, p, K);
    asm volatile("cp.async.commit_group;");
    asm volatile("cp.async.wait_group 1;");
    __syncthreads();
    ldsm_frags(0, smem_u32, 0);

    int cur_st = 0;
    for (;;) {
        if (tid == 0) sm_next[0] = atomicAdd(&g_ctr1, 1u);

        float acc[4][8][4];
        #pragma unroll
        for (int a = 0; a < 4; a++)
            #pragma unroll
            for (int b = 0; b < 8; b++)
                #pragma unroll
                for (int c = 0; c < 4; c++) acc[a][b][c] = 0.f;

        unsigned t_next = 0;
        bool has_next = false;
        bool prefetched = true;   // cross-tile prefetch happened for next tile
        int nm = 0, nn2 = 0, nk = 0, Kn = K, KTn = KT;
        bool is1n = is1;
        const __half *pAn = pA, *pBn = pB;

        for (int kt = 0; kt < KT; ++kt) {
            if (kt == KT - 2) {
                t_next = sm_next[0];
                has_next = t_next < NT_ALL;
                if (has_next) {
                    decode(t_next, nm, nn2, nk, Kn, KTn, is1n);
                    if (!is1n) {
                        // NON-BLOCKING readiness check (uniform via smem flag)
                        if (tid == 0)
                            sm_flag[0] = (g_rowcnt[nm >> 7] >= 24u) ? 1u : 0u;
                        __syncthreads();
                        prefetched = (sm_flag[0] != 0u);
                    }
                    pAn = (is1n ? g_A : g_H) + (size_t)(nm + lrow) * Kn + lcol * 8 + nk;
                    pBn = (is1n ? g_Wi : g_Wf) + (size_t)(nn2 + lrow) * Kn + lcol * 8 + nk;
                }
            }

            const uint32_t base = smem_u32 + cur_st * STAGE_B;
            int p_st = cur_st + 2; if (p_st >= NSTAGE) p_st -= NSTAGE;
            const bool tail = (kt + 2 >= KT);
            const bool do_cp = !tail || (has_next && prefetched);
            const int koff = (tail ? (kt + 2 - KT) : (kt + 2)) * BK;
            const __half* qA = tail ? pAn : pA;
            const __half* qB = tail ? pBn : pB;
            const int qK = tail ? Kn : K;

            #pragma unroll
            for (int ks = 0; ks < 4; ++ks) {
                const int cur = ks & 1;
                if (ks < 3) ldsm_frags(cur ^ 1, base, ks + 1);
                // first mma half-burst (mt 0..1)
                #pragma unroll
                for (int mt = 0; mt < 2; ++mt)
                    #pragma unroll
                    for (int nt = 0; nt < 8; ++nt) {
                        uint32_t b0 = bF[cur][nt >> 1][(nt & 1) * 2];
                        uint32_t b1 = bF[cur][nt >> 1][(nt & 1) * 2 + 1];
                        mma_f16(acc[mt][nt], aF[cur][mt], b0, b1);
                    }
                if (do_cp) load_part(p_st, koff, qA, qB, ks, qK);
                if (ks == 3) asm volatile("cp.async.commit_group;");
                // second mma half-burst (mt 2..3)
                #pragma unroll
                for (int mt = 2; mt < 4; ++mt)
                    #pragma unroll
                    for (int nt = 0; nt < 8; ++nt) {
                        uint32_t b0 = bF[cur][nt >> 1][(nt & 1) * 2];
                        uint32_t b1 = bF[cur][nt >> 1][(nt & 1) * 2 + 1];
                        mma_f16(acc[mt][nt], aF[cur][mt], b0, b1);
                    }
            }

            asm volatile("cp.async.wait_group 1;");
            __syncthreads();
            int nxt_st = cur_st + 1; if (nxt_st >= NSTAGE) nxt_st -= NSTAGE;
            if (kt + 1 < KT || (has_next && prefetched))
                ldsm_frags(0, smem_u32 + nxt_st * STAGE_B, 0);
            cur_st = nxt_st;
        }

        // ---------------- epilogue ----------------
        if (is1) {
            #pragma unroll
            for (int mt = 0; mt < 4; ++mt)
                #pragma unroll
                for (int nt = 0; nt < 8; ++nt) {
                    int n = n_blk + wn * 64 + nt * 8 + (lane & 3) * 2;
                    float b0 = bias1[n], b1 = bias1[n + 1];
                    #pragma unroll
                    for (int h = 0; h < 2; ++h) {
                        int m = m_blk + wm * 64 + mt * 16 + (lane >> 2) + h * 8;
                        float x0 = acc[mt][nt][2 * h + 0] + b0;
                        float x1 = acc[mt][nt][2 * h + 1] + b1;
                        __half2 hv = __floats2half2_rn(gelu_exact(x0), gelu_exact(x1));
                        *reinterpret_cast<__half2*>(&g_H[(size_t)m * D_FF + n]) = hv;
                    }
                }
            __threadfence();
            __syncthreads();
            if (tid == 0) atomicAdd(&g_rowcnt[m_blk >> 7], 1u);
        } else {
            __half* Pout = (k_base == 0) ? g_P : (k_base == 1024 ? g_P2 : g_P3);
            #pragma unroll
            for (int mt = 0; mt < 4; ++mt)
                #pragma unroll
                for (int nt = 0; nt < 8; ++nt) {
                    int n = n_blk + wn * 64 + nt * 8 + (lane & 3) * 2;
                    #pragma unroll
                    for (int h = 0; h < 2; ++h) {
                        int m = m_blk + wm * 64 + mt * 16 + (lane >> 2) + h * 8;
                        __half2 hv = __floats2half2_rn(acc[mt][nt][2 * h],
                                                       acc[mt][nt][2 * h + 1]);
                        *reinterpret_cast<__half2*>(&Pout[(size_t)m * D_MODEL + n]) = hv;
                    }
                }
        }

        if (!has_next) break;

        if (!prefetched) {
            // next tile is gemm2 whose inputs weren't ready mid-tile: spin AFTER
            // our own epilogue/increment (deadlock-free), then refill pipeline.
            volatile unsigned* rc = &g_rowcnt[nm >> 7];
            while (*rc < 24u) { }
            __threadfence();
            __syncthreads();
            int st1 = cur_st + 1; if (st1 >= NSTAGE) st1 -= NSTAGE;
            #pragma unroll
            for (int p = 0; p < 4; ++p) load_part(cur_st, 0, pAn, pBn, p, Kn);
            asm volatile("cp.async.commit_group;");
            #pragma unroll
            for (int p = 0; p < 4; ++p) load_part(st1, BK, pAn, pBn, p, Kn);
            asm volatile("cp.async.commit_group;");
            asm volatile("cp.async.wait_group 1;");
            __syncthreads();
            ldsm_frags(0, smem_u32 + cur_st * STAGE_B, 0);
        }

        t = t_next; m_blk = nm; n_blk = nn2; k_base = nk;
        K = Kn; KT = KTn; is1 = is1n;
        pA = pAn; pB = pBn;
    }
}

// ---------------- launch ---------------------------------------------------------
extern "C" void kernel_launch(void* const* d_in, const int* in_sizes, int n_in,
                              void* d_out, int out_size) {
    (void)in_sizes; (void)n_in; (void)out_size;
    const float* hidden = (const float*)d_in[0];
    // d_in[1..6] = Wq,bq,Wk,bk,Wv,bv — dead (q/k/v overwritten by constants)
    const float* Wo   = (const float*)d_in[7];
    const float* bo   = (const float*)d_in[8];
    const float* ln1g = (const float*)d_in[9];
    const float* ln1b = (const float*)d_in[10];
    const float* Wi   = (const float*)d_in[11];
    const float* bi   = (const float*)d_in[12];
    const float* Wf   = (const float*)d_in[13];
    const float* bf_  = (const float*)d_in[14];
    const float* ln2g = (const float*)d_in[15];
    const float* ln2b = (const float*)d_in[16];
    float* out = (float*)d_out;

    cudaFuncSetAttribute(gemm_fused, cudaFuncAttributeMaxDynamicSharedMemorySize, SMEM_GEMM);

    rowsum_kernel<<<96, 256>>>(Wo, bo);
    prep_kernel<<<LN1_BLOCKS + CONV_BLOCKS, 256>>>(hidden, ln1g, ln1b, Wi, Wf);

    gemm_fused<<<GRIDP, 128, SMEM_GEMM>>>(bi);

    ln2_kernel<<<MROWS / 8, 256>>>(ln2g, ln2b, bf_, out);
}

// round 16
// speedup vs baseline: 1.1271x; 1.0102x over previous
#include <cuda_runtime.h>
#include <cuda_fp16.h>
#include <stdint.h>

#define D_MODEL 768
#define D_FF    3072
#define MROWS   8192   // B*S = 4*2048
#define LN_EPS  1e-12f
#define GRIDP   296    // persistent CTA count (2 per SM on 148-SM die)

// ---------------- scratch (__device__ globals; no runtime allocation) ----------
__device__ float   g_c[D_MODEL];
__device__ __half  g_A[(size_t)MROWS * D_MODEL];    // LN1 output (also ln2 residual)
__device__ __half  g_Wi[(size_t)D_FF * D_MODEL];
__device__ __half  g_Wf[(size_t)D_MODEL * D_FF];
__device__ __half  g_H[(size_t)MROWS * D_FF];
__device__ __half  g_P[(size_t)MROWS * D_MODEL];
__device__ __half  g_P2[(size_t)MROWS * D_MODEL];
__device__ unsigned g_ctr1;
__device__ unsigned g_rowcnt[64];   // gemm1 completion counters per 128-row block

// ---------------- helpers --------------------------------------------------------
__device__ __forceinline__ float gelu_exact(float x) {
    return 0.5f * x * (1.0f + erff(x * 0.7071067811865476f));
}

__device__ __forceinline__ void ldsm4(uint32_t (&r)[4], uint32_t addr) {
    asm volatile("ldmatrix.sync.aligned.m8n8.x4.shared.b16 {%0,%1,%2,%3}, [%4];"
                 : "=r"(r[0]), "=r"(r[1]), "=r"(r[2]), "=r"(r[3])
                 : "r"(addr));
}

__device__ __forceinline__ void mma_f16(float (&c)[4], const uint32_t (&a)[4],
                                        uint32_t b0, uint32_t b1) {
    asm volatile(
        "mma.sync.aligned.m16n8k16.row.col.f32.f16.f16.f32 "
        "{%0,%1,%2,%3},{%4,%5,%6,%7},{%8,%9},{%0,%1,%2,%3};"
        : "+f"(c[0]), "+f"(c[1]), "+f"(c[2]), "+f"(c[3])
        : "r"(a[0]), "r"(a[1]), "r"(a[2]), "r"(a[3]), "r"(b0), "r"(b1));
}

__device__ __forceinline__ void cp16(uint32_t saddr, const void* g) {
    asm volatile("cp.async.cg.shared.global [%0], [%1], 16;" ::"r"(saddr), "l"(g));
}

// warp butterfly reduce (all lanes get result)
__device__ __forceinline__ void warp_reduce2(float& s, float& s2) {
    #pragma unroll
    for (int o = 16; o; o >>= 1) {
        s  += __shfl_xor_sync(0xffffffffu, s,  o);
        s2 += __shfl_xor_sync(0xffffffffu, s2, o);
    }
}

// ---------------- small kernels --------------------------------------------------
// also resets the dynamic-scheduler state each replay; float4-vectorized rowsum
__global__ void rowsum_kernel(const float* __restrict__ Wo, const float* __restrict__ bo) {
    if (blockIdx.x == 0) {
        if (threadIdx.x == 0) g_ctr1 = 0;
        if (threadIdx.x < 64) g_rowcnt[threadIdx.x] = 0;
    }
    int gw = (blockIdx.x * blockDim.x + threadIdx.x) >> 5;
    int lane = threadIdx.x & 31;
    if (gw >= D_MODEL) return;
    const float4* r = reinterpret_cast<const float4*>(Wo + (size_t)gw * D_MODEL);
    float s = 0.f;
    #pragma unroll
    for (int i = 0; i < 6; i++) {
        float4 v = r[lane + 32 * i];
        s += v.x + v.y + v.z + v.w;
    }
    #pragma unroll
    for (int o = 16; o; o >>= 1) s += __shfl_down_sync(0xffffffffu, s, o);
    if (lane == 0) g_c[gw] = 0.01f * s + bo[gw];
}

// merged: blocks [0,1024) = ln1 (warp per row, 8 rows/block);
//         blocks [1024, 1024+4608) = weight conversion
#define LN1_BLOCKS  1024
#define CONV_BLOCKS 4608   // 2*(D_FF*D_MODEL/4)/256
__global__ void __launch_bounds__(256) prep_kernel(
        const float* __restrict__ hidden,
        const float* __restrict__ gam, const float* __restrict__ bet,
        const float* __restrict__ Wi, const float* __restrict__ Wf) {
    int bid = blockIdx.x;
    if (bid < LN1_BLOCKS) {
        int warp = threadIdx.x >> 5, lane = threadIdx.x & 31;
        int row = bid * 8 + warp;
        const float4* xr = reinterpret_cast<const float4*>(hidden + (size_t)row * D_MODEL);
        const float4* cr = reinterpret_cast<const float4*>(g_c);
        float4 v[6];
        float s = 0.f, s2 = 0.f;
        #pragma unroll
        for (int i = 0; i < 6; i++) {
            float4 x = xr[lane + 32 * i];
            float4 c = cr[lane + 32 * i];
            x.x += c.x; x.y += c.y; x.z += c.z; x.w += c.w;
            v[i] = x;
            s  += x.x + x.y + x.z + x.w;
            s2 += x.x * x.x + x.y * x.y + x.z * x.z + x.w * x.w;
        }
        warp_reduce2(s, s2);
        float mean = s * (1.f / D_MODEL);
        float var = s2 * (1.f / D_MODEL) - mean * mean;
        float rstd = rsqrtf(var + LN_EPS);
        uint2* outp = reinterpret_cast<uint2*>(g_A + (size_t)row * D_MODEL);
        const float4* gr = reinterpret_cast<const float4*>(gam);
        const float4* br = reinterpret_cast<const float4*>(bet);
        #pragma unroll
        for (int i = 0; i < 6; i++) {
            float4 g = gr[lane + 32 * i];
            float4 b = br[lane + 32 * i];
            float4 a;
            a.x = (v[i].x - mean) * rstd * g.x + b.x;
            a.y = (v[i].y - mean) * rstd * g.y + b.y;
            a.z = (v[i].z - mean) * rstd * g.z + b.z;
            a.w = (v[i].w - mean) * rstd * g.w + b.w;
            __half2 h0 = __floats2half2_rn(a.x, a.y);
            __half2 h1 = __floats2half2_rn(a.z, a.w);
            outp[lane + 32 * i] = make_uint2(*(uint32_t*)&h0, *(uint32_t*)&h1);
        }
    } else {
        constexpr int n4 = D_FF * D_MODEL / 4;
        int i = (bid - LN1_BLOCKS) * 256 + threadIdx.x;
        const float* src;
        __half* Wh;
        int j;
        if (i < n4) { src = Wi; Wh = g_Wi; j = i; }
        else        { src = Wf; Wh = g_Wf; j = i - n4; }
        float4 v = reinterpret_cast<const float4*>(src)[j];
        __half2 h01 = __floats2half2_rn(v.x, v.y);
        __half2 h23 = __floats2half2_rn(v.z, v.w);
        reinterpret_cast<uint2*>(Wh)[j] =
            make_uint2(*(uint32_t*)&h01, *(uint32_t*)&h23);
    }
}

// out = LN(P0 + P1 + A + bf); warp per row, 8 rows/block, uint4 half loads
__global__ void __launch_bounds__(256) ln2_kernel(
        const float* __restrict__ gam, const float* __restrict__ bet,
        const float* __restrict__ bf, float* __restrict__ out) {
    int warp = threadIdx.x >> 5, lane = threadIdx.x & 31;
    int row = blockIdx.x * 8 + warp;
    size_t rbase8 = (size_t)row * (D_MODEL / 8);   // uint4 = 8 halves
    const uint4* p0 = reinterpret_cast<const uint4*>(g_P)  + rbase8;
    const uint4* p1 = reinterpret_cast<const uint4*>(g_P2) + rbase8;
    const uint4* pa = reinterpret_cast<const uint4*>(g_A)  + rbase8;
    const float4* bfr = reinterpret_cast<const float4*>(bf);
    float4 v[6];
    float s = 0.f, s2 = 0.f;
    #pragma unroll
    for (int i = 0; i < 3; i++) {
        int idx = lane + 32 * i;               // uint4 index (8 halves)
        uint4 u0 = p0[idx], u1 = p1[idx], ua = pa[idx];
        const uint32_t* w0 = &u0.x;
        const uint32_t* w1 = &u1.x;
        const uint32_t* wa = &ua.x;
        #pragma unroll
        for (int h = 0; h < 2; h++) {          // two float4 outputs per uint4
            float2 a0 = __half22float2(*(__half2*)&w0[2 * h]);
            float2 a1 = __half22float2(*(__half2*)&w0[2 * h + 1]);
            float2 b0 = __half22float2(*(__half2*)&w1[2 * h]);
            float2 b1 = __half22float2(*(__half2*)&w1[2 * h + 1]);
            float2 t0 = __half22float2(*(__half2*)&wa[2 * h]);
            float2 t1 = __half22float2(*(__half2*)&wa[2 * h + 1]);
            float4 bv = bfr[2 * idx + h];
            float4 x;
            x.x = a0.x + b0.x + t0.x + bv.x;
            x.y = a0.y + b0.y + t0.y + bv.y;
            x.z = a1.x + b1.x + t1.x + bv.z;
            x.w = a1.y + b1.y + t1.y + bv.w;
            v[2 * i + h] = x;
            s  += x.x + x.y + x.z + x.w;
            s2 += x.x * x.x + x.y * x.y + x.z * x.z + x.w * x.w;
        }
    }
    warp_reduce2(s, s2);
    float mean = s * (1.f / D_MODEL);
    float var = s2 * (1.f / D_MODEL) - mean * mean;
    float rstd = rsqrtf(var + LN_EPS);
    const float4* gr = reinterpret_cast<const float4*>(gam);
    const float4* br = reinterpret_cast<const float4*>(bet);
    float4* op = reinterpret_cast<float4*>(out) + (size_t)row * (D_MODEL / 4);
    #pragma unroll
    for (int i = 0; i < 3; i++) {
        int idx = lane + 32 * i;
        #pragma unroll
        for (int h = 0; h < 2; h++) {
            int fi = 2 * idx + h;
            float4 g = gr[fi];
            float4 b = br[fi];
            float4 o;
            o.x = (v[2 * i + h].x - mean) * rstd * g.x + b.x;
            o.y = (v[2 * i + h].y - mean) * rstd * g.y + b.y;
            o.z = (v[2 * i + h].z - mean) * rstd * g.z + b.z;
            o.w = (v[2 * i + h].w - mean) * rstd * g.w + b.w;
            op[fi] = o;
        }
    }
}

// ---------------- fused persistent GEMM (both phases, one kernel) ----------------
// Tiles 0..1535:    gemm1  C = gelu(A@Wi^T + bi) -> g_H    (K=768,  KT=12)
// Tiles 1536..2303: gemm2  split-K2 fp16 partials -> g_P*  (Kc=1536, KT=24)
// Cross-phase dataflow guarded by g_rowcnt. The readiness check mid-tile is
// NON-BLOCKING; if not ready, the CTA finishes its tile (incl. its own rowcnt
// increment) and only then spins + refills -> provably deadlock-free.
#define BK 64
#define LDT 72                        // padded smem row elems; 144B stride
#define TILE_B 18432                  // 128*72*2 per operand
#define STAGE_B 36864
#define NSTAGE 3
#define SMEM_GEMM (NSTAGE * STAGE_B + 16)
#define NT1 1536
#define NT_ALL 2304

__global__ void __launch_bounds__(128, 2) gemm_fused(const float* __restrict__ bias1) {
    extern __shared__ char smem[];
    const uint32_t smem_u32 = (uint32_t)__cvta_generic_to_shared(smem);
    volatile unsigned* sm_next = (volatile unsigned*)(smem + NSTAGE * STAGE_B);
    volatile unsigned* sm_flag = (volatile unsigned*)(smem + NSTAGE * STAGE_B + 4);

    const int tid = threadIdx.x;
    const int lane = tid & 31;
    const int warp = tid >> 5;
    const int wm = warp >> 1;
    const int wn = warp & 1;
    const int lrow = tid >> 3;        // 0..15
    const int lcol = tid & 7;         // 0..7

    __shared__ unsigned s_t0;
    if (tid == 0) s_t0 = atomicAdd(&g_ctr1, 1u);
    __syncthreads();
    unsigned t = s_t0;
    if (t >= NT_ALL) return;

    auto decode = [&](unsigned tt, int& mb, int& nb, int& kb, int& kk, int& ktn, bool& is1) {
        if (tt < NT1) {
            is1 = true;  nb = (tt % 24) * 128; mb = (tt / 24) * 128; kb = 0;
            kk = D_MODEL; ktn = 12;
        } else {
            unsigned u = tt - NT1;
            is1 = false; nb = (u % 6) * 128; mb = ((u / 6) % 64) * 128; kb = (u / 384) * 1536;
            kk = D_FF; ktn = 24;
        }
    };

    int m_blk, n_blk, k_base, K, KT;
    bool is1;
    decode(t, m_blk, n_blk, k_base, K, KT, is1);   // first 296 tiles are all gemm1

    const __half* pA = (is1 ? g_A : g_H) + (size_t)(m_blk + lrow) * K + lcol * 8 + k_base;
    const __half* pB = (is1 ? g_Wi : g_Wf) + (size_t)(n_blk + lrow) * K + lcol * 8 + k_base;

    const uint32_t sm_woff = (uint32_t)(lrow * 144 + lcol * 16);

    // one quarter (2x16 rows of A and B) of a BK=64 slab; stride = row pitch (elems)
    auto load_part = [&](int s, int koff, const __half* a, const __half* b, int part,
                         int stride) {
        uint32_t base = smem_u32 + s * STAGE_B + sm_woff + (uint32_t)(part * 32 * 144);
        const __half* ga = a + (size_t)(part * 32) * stride + koff;
        const __half* gb = b + (size_t)(part * 32) * stride + koff;
        cp16(base,                       ga);
        cp16(base + TILE_B,              gb);
        cp16(base + 16 * 144,            ga + (size_t)16 * stride);
        cp16(base + 16 * 144 + TILE_B,   gb + (size_t)16 * stride);
    };

    const int a_row = wm * 64 + (lane & 15);
    const int a_k = (lane >> 4) * 8;
    const int b_row = wn * 64 + (lane & 7) + ((lane >> 4) & 1) * 8;
    const int b_k = ((lane >> 3) & 1) * 8;

    uint32_t aF[2][4][4], bF[2][4][4];
    auto ldsm_frags = [&](int buf, uint32_t base, int ks) {
        const int k0 = ks * 16;
        #pragma unroll
        for (int mt = 0; mt < 4; ++mt)
            ldsm4(aF[buf][mt], base + (uint32_t)((a_row + mt * 16) * LDT + k0 + a_k) * 2);
        #pragma unroll
        for (int np = 0; np < 4; ++np)
            ldsm4(bF[buf][np], base + TILE_B +
                                   (uint32_t)((b_row + np * 16) * LDT + k0 + b_k) * 2);
    };

    // preamble: slabs 0 and 1 of first tile; preload ks0 frags of slab 0
    #pragma unroll
    for (int p = 0; p < 4; ++p) load_part(0, 0, pA, pB, p, K);
    asm volatile("cp.async.commit_group;");
    #pragma unroll
    for (int p = 0; p < 4; ++p) load_part(1, BK, pA, pB, p, K);
    asm volatile("cp.async.commit_group;");
    asm volatile("cp.async.wait_group 1;");
    __syncthreads();
    ldsm_frags(0, smem_u32, 0);

    int cur_st = 0;
    for (;;) {
        if (tid == 0) sm_next[0] = atomicAdd(&g_ctr1, 1u);

        float acc[4][8][4];
        #pragma unroll
        for (int a = 0; a < 4; a++)
            #pragma unroll
            for (int b = 0; b < 8; b++)
                #pragma unroll
                for (int c = 0; c < 4; c++) acc[a][b][c] = 0.f;

        unsigned t_next = 0;
        bool has_next = false;
        bool prefetched = true;   // cross-tile prefetch happened for next tile
        int nm = 0, nn2 = 0, nk = 0, Kn = K, KTn = KT;
        bool is1n = is1;
        const __half *pAn = pA, *pBn = pB;

        for (int kt = 0; kt < KT; ++kt) {
            if (kt == KT - 2) {
                t_next = sm_next[0];
                has_next = t_next < NT_ALL;
                if (has_next) {
                    decode(t_next, nm, nn2, nk, Kn, KTn, is1n);
                    if (!is1n) {
                        // NON-BLOCKING readiness check (uniform via smem flag)
                        if (tid == 0)
                            sm_flag[0] = (g_rowcnt[nm >> 7] >= 24u) ? 1u : 0u;
                        __syncthreads();
                        prefetched = (sm_flag[0] != 0u);
                    }
                    pAn = (is1n ? g_A : g_H) + (size_t)(nm + lrow) * Kn + lcol * 8 + nk;
                    pBn = (is1n ? g_Wi : g_Wf) + (size_t)(nn2 + lrow) * Kn + lcol * 8 + nk;
                }
            }

            const uint32_t base = smem_u32 + cur_st * STAGE_B;
            int p_st = cur_st + 2; if (p_st >= NSTAGE) p_st -= NSTAGE;
            const bool tail = (kt + 2 >= KT);
            const bool do_cp = !tail || (has_next && prefetched);
            const int koff = (tail ? (kt + 2 - KT) : (kt + 2)) * BK;
            const __half* qA = tail ? pAn : pA;
            const __half* qB = tail ? pBn : pB;
            const int qK = tail ? Kn : K;

            #pragma unroll
            for (int ks = 0; ks < 4; ++ks) {
                const int cur = ks & 1;
                if (ks < 3) ldsm_frags(cur ^ 1, base, ks + 1);
                // first mma half-burst (mt 0..1)
                #pragma unroll
                for (int mt = 0; mt < 2; ++mt)
                    #pragma unroll
                    for (int nt = 0; nt < 8; ++nt) {
                        uint32_t b0 = bF[cur][nt >> 1][(nt & 1) * 2];
                        uint32_t b1 = bF[cur][nt >> 1][(nt & 1) * 2 + 1];
                        mma_f16(acc[mt][nt], aF[cur][mt], b0, b1);
                    }
                if (do_cp) load_part(p_st, koff, qA, qB, ks, qK);
                if (ks == 3) asm volatile("cp.async.commit_group;");
                // second mma half-burst (mt 2..3)
                #pragma unroll
                for (int mt = 2; mt < 4; ++mt)
                    #pragma unroll
                    for (int nt = 0; nt < 8; ++nt) {
                        uint32_t b0 = bF[cur][nt >> 1][(nt & 1) * 2];
                        uint32_t b1 = bF[cur][nt >> 1][(nt & 1) * 2 + 1];
                        mma_f16(acc[mt][nt], aF[cur][mt], b0, b1);
                    }
            }

            asm volatile("cp.async.wait_group 1;");
            __syncthreads();
            int nxt_st = cur_st + 1; if (nxt_st >= NSTAGE) nxt_st -= NSTAGE;
            if (kt + 1 < KT || (has_next && prefetched))
                ldsm_frags(0, smem_u32 + nxt_st * STAGE_B, 0);
            cur_st = nxt_st;
        }

        // ---------------- epilogue ----------------
        if (is1) {
            #pragma unroll
            for (int mt = 0; mt < 4; ++mt)
                #pragma unroll
                for (int nt = 0; nt < 8; ++nt) {
                    int n = n_blk + wn * 64 + nt * 8 + (lane & 3) * 2;
                    float b0 = bias1[n], b1 = bias1[n + 1];
                    #pragma unroll
                    for (int h = 0; h < 2; ++h) {
                        int m = m_blk + wm * 64 + mt * 16 + (lane >> 2) + h * 8;
                        float x0 = acc[mt][nt][2 * h + 0] + b0;
                        float x1 = acc[mt][nt][2 * h + 1] + b1;
                        __half2 hv = __floats2half2_rn(gelu_exact(x0), gelu_exact(x1));
                        *reinterpret_cast<__half2*>(&g_H[(size_t)m * D_FF + n]) = hv;
                    }
                }
            __threadfence();
            __syncthreads();
            if (tid == 0) atomicAdd(&g_rowcnt[m_blk >> 7], 1u);
        } else {
            __half* Pout = (k_base == 0) ? g_P : g_P2;
            #pragma unroll
            for (int mt = 0; mt < 4; ++mt)
                #pragma unroll
                for (int nt = 0; nt < 8; ++nt) {
                    int n = n_blk + wn * 64 + nt * 8 + (lane & 3) * 2;
                    #pragma unroll
                    for (int h = 0; h < 2; ++h) {
                        int m = m_blk + wm * 64 + mt * 16 + (lane >> 2) + h * 8;
                        __half2 hv = __floats2half2_rn(acc[mt][nt][2 * h],
                                                       acc[mt][nt][2 * h + 1]);
                        *reinterpret_cast<__half2*>(&Pout[(size_t)m * D_MODEL + n]) = hv;
                    }
                }
        }

        if (!has_next) break;

        if (!prefetched) {
            // next tile is gemm2 whose inputs weren't ready mid-tile: spin AFTER
            // our own epilogue/increment (deadlock-free), then refill pipeline.
            volatile unsigned* rc = &g_rowcnt[nm >> 7];
            while (*rc < 24u) { }
            __threadfence();
            __syncthreads();
            int st1 = cur_st + 1; if (st1 >= NSTAGE) st1 -= NSTAGE;
            #pragma unroll
            for (int p = 0; p < 4; ++p) load_part(cur_st, 0, pAn, pBn, p, Kn);
            asm volatile("cp.async.commit_group;");
            #pragma unroll
            for (int p = 0; p < 4; ++p) load_part(st1, BK, pAn, pBn, p, Kn);
            asm volatile("cp.async.commit_group;");
            asm volatile("cp.async.wait_group 1;");
            __syncthreads();
            ldsm_frags(0, smem_u32 + cur_st * STAGE_B, 0);
        }

        t = t_next; m_blk = nm; n_blk = nn2; k_base = nk;
        K = Kn; KT = KTn; is1 = is1n;
        pA = pAn; pB = pBn;
    }
}

// ---------------- launch ---------------------------------------------------------
extern "C" void kernel_launch(void* const* d_in, const int* in_sizes, int n_in,
                              void* d_out, int out_size) {
    (void)in_sizes; (void)n_in; (void)out_size;
    const float* hidden = (const float*)d_in[0];
    // d_in[1..6] = Wq,bq,Wk,bk,Wv,bv — dead (q/k/v overwritten by constants)
    const float* Wo   = (const float*)d_in[7];
    const float* bo   = (const float*)d_in[8];
    const float* ln1g = (const float*)d_in[9];
    const float* ln1b = (const float*)d_in[10];
    const float* Wi   = (const float*)d_in[11];
    const float* bi   = (const float*)d_in[12];
    const float* Wf   = (const float*)d_in[13];
    const float* bf_  = (const float*)d_in[14];
    const float* ln2g = (const float*)d_in[15];
    const float* ln2b = (const float*)d_in[16];
    float* out = (float*)d_out;

    cudaFuncSetAttribute(gemm_fused, cudaFuncAttributeMaxDynamicSharedMemorySize, SMEM_GEMM);

    rowsum_kernel<<<96, 256>>>(Wo, bo);
    prep_kernel<<<LN1_BLOCKS + CONV_BLOCKS, 256>>>(hidden, ln1g, ln1b, Wi, Wf);

    gemm_fused<<<GRIDP, 128, SMEM_GEMM>>>(bi);

    ln2_kernel<<<MROWS / 8, 256>>>(ln2g, ln2b, bf_, out);
}